// round 16
// baseline (speedup 1.0000x reference)
#include <cuda_runtime.h>
#include <cuda_fp16.h>
#include <math.h>

// Problem constants
#define BB 2
#define DD 128
#define HH 128
#define WW 128
#define NVOX (BB*DD*HH*WW)          // 4194304
#define PLANE (HH*WW)               // 16384

// ---------------- static device scratch (no runtime allocation) ----------------
// interleaved per voxel: {gauss_wh(s), gauss_wh(s^2), gauss_wh(d), gauss_wh(d^2)}
__device__ __align__(16) float4 g_buf4[NVOX];
__device__ __align__(16) __half g_gm[2u*NVOX];  // gradient magnitude (fp16): pred, target
__device__ double g_part[3][64];    // partial sums: mse, ssim, gme
__device__ unsigned g_mm[4];        // minp, maxp, mint, maxt (float bits, all >0)

// ---------------- helpers ----------------
__device__ __forceinline__ int refl(int x) {      // jnp 'reflect' (no edge repeat)
    return x < 0 ? -x : (x > 127 ? 254 - x : x);
}

__device__ __forceinline__ void load_gauss(float* G) {
    if (threadIdx.x == 0 && threadIdx.y == 0) {
        float tmp[11]; float s = 0.f;
        #pragma unroll
        for (int i = 0; i < 11; i++) {
            float o = (float)(i - 5);
            tmp[i] = expf(-(o*o) / 4.5f);   // 2*1.5^2 = 4.5
            s += tmp[i];
        }
        #pragma unroll
        for (int i = 0; i < 11; i++) G[i] = tmp[i] / s;
    }
}

// Block-wide sum -> double partial slot (flat tid, block size multiple of 32, <=1024)
__device__ __forceinline__ void block_add(float v, int slot) {
    #pragma unroll
    for (int o = 16; o > 0; o >>= 1) v += __shfl_down_sync(0xffffffffu, v, o);
    __shared__ float red[32];
    int tidf = threadIdx.y * blockDim.x + threadIdx.x;
    int nthr = blockDim.x * blockDim.y;
    int lane = tidf & 31, wid = tidf >> 5;
    if (lane == 0) red[wid] = v;
    __syncthreads();
    int nw = (nthr + 31) >> 5;
    if (wid == 0) {
        float x = (lane < nw) ? red[lane] : 0.f;
        #pragma unroll
        for (int o = 16; o > 0; o >>= 1) x += __shfl_down_sync(0xffffffffu, x, o);
        if (lane == 0) atomicAdd(&g_part[slot][blockIdx.x & 63], (double)x);
    }
}

// ---------------- kernels ----------------
__global__ void init_kernel() {
    int t = threadIdx.x;
    if (t < 64) { g_part[0][t] = 0.0; g_part[1][t] = 0.0; g_part[2][t] = 0.0; }
    if (t == 0) {
        g_mm[0] = 0x7F800000u; g_mm[1] = 0u;
        g_mm[2] = 0x7F800000u; g_mm[3] = 0u;
    }
}

// Fused W+H Gaussian, BOTH channel pairs per block (block (128,2)):
// half y stages row r0+y (loading p,t ONCE, deriving s AND d -> both q arrays),
// then convs ITS pair (y=0: s, y=1: d) over both staged rows. Input reads and
// LDG/address chains halved vs split-pair blocks; conv work, win regs, and
// barrier cadence per thread unchanged. MSE accumulated by the stager.
#define HCH 4
#define HROWS (HH/HCH)   // 32
__global__ __launch_bounds__(256) void fused_wh(const float* __restrict__ p,
                                                const float* __restrict__ t) {
    __shared__ float G[11];
    __shared__ float q[2][4][WW+10];   // [pair][buf][5 zero | WW data | 5 zero]
    load_gauss(G);
    int bd = blockIdx.x;
    int h0 = blockIdx.y * HROWS;
    int w    = threadIdx.x;
    int half = threadIdx.y;            // stager row parity AND conv pair
    size_t sbase = (size_t)bd * PLANE;
    float2* __restrict__ dst = reinterpret_cast<float2*>(g_buf4) + half;

    // zero the padding once (each half zeroes its own pair's bufs)
    if (w < 5) {
        #pragma unroll
        for (int bq = 0; bq < 4; bq++) {
            q[half][bq][w]      = 0.f;
            q[half][bq][WW+5+w] = 0.f;
        }
    }

    float2 win[12];
    float msea = 0.f;

    // pending row for this thread: r0 + half (prefetched)
    int r0 = h0 - 5;
    float pv = 0.f, tv = 0.f;
    { int rr = r0 + half;
      if ((unsigned)rr < (unsigned)HH) { pv = p[sbase + (size_t)rr*WW + w];
                                          tv = t[sbase + (size_t)rr*WW + w]; } }
    int bp = 0;

    // STEP2: stage own row (s AND d) -> q[0..1][bp+half], prefetch next own row,
    // barrier, conv BOTH rows of OWN pair -> DA,DB. Buffer bp is rewritten two
    // barriers after its conv-read (4 bufs) -> race-free.
    #define STEP2(DA, DB)                                                               \
    {                                                                                   \
        int rr = r0 + half;                                                             \
        if ((unsigned)rr < (unsigned)HH) {                                              \
            float sv = pv + tv, dv = pv - tv;                                           \
            q[0][bp + half][w+5] = sv;                                                  \
            q[1][bp + half][w+5] = dv;                                                  \
            if (rr >= h0 && rr < h0 + HROWS) msea += dv*dv;                             \
        }                                                                               \
        int rn = rr + 2;                                                                \
        float pn = 0.f, tn = 0.f;                                                       \
        if ((unsigned)rn < (unsigned)HH) { pn = p[sbase + (size_t)rn*WW + w];           \
                                            tn = t[sbase + (size_t)rn*WW + w]; }        \
        __syncthreads();                                                                \
        bool oka = ((unsigned)r0 < (unsigned)HH);                                       \
        bool okb = ((unsigned)(r0+1) < (unsigned)HH);                                   \
        float a0=0.f, a1=0.f, b0=0.f, b1=0.f;                                           \
        if (oka) {                                                                      \
            _Pragma("unroll")                                                           \
            for (int k = 0; k < 11; k++) {                                              \
                float v = q[half][bp][w+k]; float gv = G[k] * v;                        \
                a0 += gv; a1 += gv * v;                                                 \
            }                                                                           \
        }                                                                               \
        if (okb) {                                                                      \
            _Pragma("unroll")                                                           \
            for (int k = 0; k < 11; k++) {                                              \
                float v = q[half][bp+1][w+k]; float gv = G[k] * v;                      \
                b0 += gv; b1 += gv * v;                                                 \
            }                                                                           \
        }                                                                               \
        DA = make_float2(a0, a1); DB = make_float2(b0, b1);                             \
        pv = pn; tv = tn; r0 += 2; bp ^= 2;                                             \
    }

    // preload win[0..11] = rows h0-5 .. h0+6 (6 pairs)
    #pragma unroll
    for (int k = 0; k < 6; k++) {
        STEP2(win[2*k], win[2*k+1]);
    }

    // main loop: 2 output rows per iteration
    for (int h = h0; h < h0 + HROWS; h += 2) {
        float a0=0.f, a1=0.f, b0=0.f, b1=0.f;
        #pragma unroll
        for (int j = 0; j < 11; j++) {
            float g = G[j];
            a0 += g * win[j].x;   a1 += g * win[j].y;
            b0 += g * win[j+1].x; b1 += g * win[j+1].y;
        }
        dst[2u*(sbase + (size_t)h*WW + w)]     = make_float2(a0, a1);
        dst[2u*(sbase + (size_t)(h+1)*WW + w)] = make_float2(b0, b1);
        #pragma unroll
        for (int j = 0; j < 10; j++) win[j] = win[j+2];
        STEP2(win[10], win[11]);
    }
    #undef STEP2

    block_add(msea, 0);
}

// Gaussian along D of the float4 channels + fused SSIM map + reduction.
// MODULAR ROTATING WINDOW: d-loop fully unrolled (DROWS=16) with slot index
// (dd+j)%11 resolved at compile time -> zero register-shift MOVs, win stays 11.
// SSIM from {gs, gs2, gd, gd2}:
//   mu_p^2+mu_t^2 = (gs^2+gd^2)/2,  2*mu_pt = (gs^2-gd^2)/2
//   2*sig_pt = ((gs2-gd2)-(gs^2-gd^2))/2,  sig_p+sig_t = ((gs2+gd2)-(gs^2+gd^2))/2
// grid: (HH, BB, DCH d-chunks), block: WW. One LDG.128 per output plane.
#define DCH 8
#define DROWS (DD/DCH)  // 16
__global__ __launch_bounds__(WW) void pass_d_ssim() {
    __shared__ float G[11];
    load_gauss(G); __syncthreads();
    int h = blockIdx.x, b = blockIdx.y, cz = blockIdx.z;
    int w = threadIdx.x;
    int d0 = cz * DROWS;
    size_t base0 = ((size_t)b*DD*HH + (size_t)h)*WW + w;
    const float4* __restrict__ src = g_buf4;

    float4 win[11];     // slot(r) = (r - (d0-5)) % 11
    #pragma unroll
    for (int j = 0; j < 11; j++) {
        int d = d0 + j - 5;
        win[j] = ((unsigned)d < (unsigned)DD)
            ? src[base0 + (size_t)d*PLANE] : make_float4(0.f,0.f,0.f,0.f);
    }

    float ssum = 0.f;
    #pragma unroll
    for (int dd = 0; dd < DROWS; dd++) {
        float gs=0.f, gs2=0.f, gd=0.f, gd2=0.f;
        #pragma unroll
        for (int j = 0; j < 11; j++) {
            const float4 v = win[(dd + j) % 11];
            float g = G[j];
            gs  += g * v.x; gs2 += g * v.y;
            gd  += g * v.z; gd2 += g * v.w;
        }
        float Av = gs*gs, Bv = gd*gd;
        float sumAB = Av + Bv, difAB = Av - Bv;
        float num = (0.5f*difAB + 1e-4f) * (0.5f*((gs2 - gd2) - difAB) + 9e-4f);
        float den = (0.5f*sumAB + 1e-4f) * (0.5f*((gs2 + gd2) - sumAB) + 9e-4f);
        ssum += num / den;

        int nd = d0 + dd + 6;
        win[dd % 11] = (nd < DD)
            ? src[base0 + (size_t)nd*PLANE] : make_float4(0.f,0.f,0.f,0.f);
    }
    block_add(ssum, 1);
}

// Sobel gradient magnitude. ALL 10 d-planes preloaded with VECTORIZED loads
// (one LDG.128 per thread per plane + 20 halo scalars per volume) and a single
// barrier, then barrier-free compute with strength-reduced separable algebra.
// gm stored as fp16 (min/max computed on the ROUNDED value for consistency).
// grid: (WW/32, HH/8, BB*16), block: (32,8). Each block: 8 output planes.
__global__ __launch_bounds__(256) void sobel_kernel(const float* __restrict__ pred,
                                                    const float* __restrict__ targ) {
    // interior cols 4..35 (16B aligned), left halo col 3, right halo col 36
    __shared__ __align__(16) float tile[10][2][10][40];   // [plane][vol][row][col]
    int tx = threadIdx.x, ty = threadIdx.y;
    int tid = ty * 32 + tx;
    int w0 = blockIdx.x * 32, h0 = blockIdx.y * 8;
    int z = blockIdx.z;
    int b = z >> 4, d0 = (z & 15) * 8;

    // ---- load all 10 planes, one barrier ----
    {
        int v = tid >> 7;                 // volume handled by this half-block
        int u = tid & 127;
        const float* __restrict__ src = v ? targ : pred;
        bool isVec  = (u < 80);
        int rv = u >> 3, c4 = u & 7;      // vector role: row rv, 4-col group c4
        bool isHalo = (u >= 80 && u < 100);
        int e = u - 80;
        int rh = e >> 1, side = e & 1;    // halo role: row rh, side L/R
        int ghv = isVec  ? refl(h0 + rv - 1) : 0;
        int ghh = isHalo ? refl(h0 + rh - 1) : 0;
        int gwh = side ? refl(w0 + 32) : refl(w0 - 1);
        int colh = side ? 36 : 3;
        #pragma unroll
        for (int i = 0; i < 10; i++) {
            int gd = refl(d0 - 1 + i);
            size_t pb = ((size_t)b*DD + gd)*PLANE;
            if (isVec) {
                float4 val = *reinterpret_cast<const float4*>(src + pb + (size_t)ghv*WW + w0 + c4*4);
                *reinterpret_cast<float4*>(&tile[i][v][rv][4 + c4*4]) = val;
            } else if (isHalo) {
                tile[i][v][rh][colh] = src[pb + (size_t)ghh*WW + gwh];
            }
        }
    }
    __syncthreads();

    // ---- compute: 2 sequential volume passes, no barriers ----
    float mnv[2], mxv[2];
    #pragma unroll
    for (int v = 0; v < 2; v++) {
        float P[3][7];
        float mn = 3.4e38f, mx = 0.f;
        #pragma unroll
        for (int i = 0; i < 10; i++) {
            const int ri = i % 3;
            {
                float ws[3], wc[3], wo[3];
                #pragma unroll
                for (int j = 0; j < 3; j++) {
                    float x0 = tile[i][v][ty+j][tx+3];
                    float x1 = tile[i][v][ty+j][tx+4];
                    float x2 = tile[i][v][ty+j][tx+5];
                    wo[j] = x0 + x1 + x2;
                    wc[j] = x2 - x0;
                    ws[j] = wo[j] + x1;
                }
                P[ri][3] = wc[0] + wc[1] + wc[2];        // P4 = o(wc)
                P[ri][0] = P[ri][3] + wc[1];             // P1 = s(wc)
                P[ri][1] = ws[2] - ws[0];                // P2 = c(ws)
                P[ri][5] = ws[0] + ws[1] + ws[2];        // P6 = o(ws)
                P[ri][2] = P[ri][5] + ws[1];             // P3 = s(ws)
                P[ri][4] = wo[2] - wo[0];                // P5 = c(wo)
                P[ri][6] = wo[0] + 2.f*wo[1] + wo[2];    // P7 = s(wo)
            }
            if (i >= 2) {
                const int dm = (i - 2) % 3, dc = (i - 1) % 3, dp = ri;
                int d = d0 + i - 2;
                float B5 = P[dm][0] + P[dc][0] + P[dp][0];
                float gx = B5 + P[dc][0];                        // Sx
                float B4 = P[dm][1] + P[dc][1] + P[dp][1];
                float gy = B4 + P[dc][1];                        // Sy
                float gz = P[dp][2] - P[dm][2];                  // Sz
                float B1 = P[dm][3] + 2.f*P[dc][3] + P[dp][3];
                float B2 = P[dm][4] + 2.f*P[dc][4] + P[dp][4];
                float B3 = P[dp][5] - P[dm][5];
                float B6 = P[dp][6] - P[dm][6];

                float sB = B1*B1 + B2*B2 + B3*B3 + B4*B4 + B5*B5 + B6*B6;
                float acc = gx*gx + gy*gy + gz*gz + 2.f*sB + 9e-6f;
                float gm = sqrtf(acc);

                __half hv = __float2half_rn(gm);
                float gmr = __half2float(hv);    // rounded value (what gme will see)

                size_t vox = (((size_t)b*DD + d)*HH + (h0 + ty))*WW + (w0 + tx);
                g_gm[(size_t)v*NVOX + vox] = hv;
                mn = fminf(mn, gmr); mx = fmaxf(mx, gmr);
            }
        }
        mnv[v] = mn; mxv[v] = mx;
    }

    // block min/max reduction (positive floats -> uint ordering)
    float mn0 = mnv[0], mx0 = mxv[0], mn1 = mnv[1], mx1 = mxv[1];
    #pragma unroll
    for (int o = 16; o > 0; o >>= 1) {
        mn0 = fminf(mn0, __shfl_down_sync(0xffffffffu, mn0, o));
        mx0 = fmaxf(mx0, __shfl_down_sync(0xffffffffu, mx0, o));
        mn1 = fminf(mn1, __shfl_down_sync(0xffffffffu, mn1, o));
        mx1 = fmaxf(mx1, __shfl_down_sync(0xffffffffu, mx1, o));
    }
    __shared__ float s4[4][8];
    int lane = tid & 31, wid = tid >> 5;
    if (lane == 0) { s4[0][wid]=mn0; s4[1][wid]=mx0; s4[2][wid]=mn1; s4[3][wid]=mx1; }
    __syncthreads();
    if (tid == 0) {
        float a = s4[0][0], bx = s4[1][0], cmin = s4[2][0], dmax = s4[3][0];
        #pragma unroll
        for (int i = 1; i < 8; i++) {
            a = fminf(a, s4[0][i]); bx = fmaxf(bx, s4[1][i]);
            cmin = fminf(cmin, s4[2][i]); dmax = fmaxf(dmax, s4[3][i]);
        }
        atomicMin(&g_mm[0], __float_as_uint(a));
        atomicMax(&g_mm[1], __float_as_uint(bx));
        atomicMin(&g_mm[2], __float_as_uint(cmin));
        atomicMax(&g_mm[3], __float_as_uint(dmax));
    }
}

// GME: mean |norm(gm_p) - norm(gm_t)|. fp16 source read as float4 = 8 halves.
__global__ __launch_bounds__(256) void gme_kernel() {
    const float4* __restrict__ gm = reinterpret_cast<const float4*>(g_gm);
    float minp = __uint_as_float(g_mm[0]), maxp = __uint_as_float(g_mm[1]);
    float mint = __uint_as_float(g_mm[2]), maxt = __uint_as_float(g_mm[3]);
    float ip = 1.f / (maxp - minp + 1e-6f);
    float it = 1.f / (maxt - mint + 1e-6f);
    const int NV8 = NVOX / 8;   // float4 records of 8 halves, per volume
    float acc = 0.f;
    for (int i = blockIdx.x*blockDim.x + threadIdx.x; i < NV8;
         i += gridDim.x*blockDim.x) {
        float4 araw = gm[i];
        float4 braw = gm[NV8 + i];
        const __half2* ah = reinterpret_cast<const __half2*>(&araw);
        const __half2* bh = reinterpret_cast<const __half2*>(&braw);
        #pragma unroll
        for (int k = 0; k < 4; k++) {
            float2 a2 = __half22float2(ah[k]);
            float2 b2 = __half22float2(bh[k]);
            acc += fabsf((a2.x - minp)*ip - (b2.x - mint)*it);
            acc += fabsf((a2.y - minp)*ip - (b2.y - mint)*it);
        }
    }
    block_add(acc, 2);
}

__global__ void finalize_kernel(float* out, int out_size) {
    if (threadIdx.x == 0) {
        double s0 = 0.0, s1 = 0.0, s2 = 0.0;
        for (int i = 0; i < 64; i++) { s0 += g_part[0][i]; s1 += g_part[1][i]; s2 += g_part[2][i]; }
        const double inv = 1.0 / (double)NVOX;
        double mse  = s0 * inv;
        double ssim = 1.0 - s1 * inv;
        double gme  = 1e-6 + s2 * inv;
        double total = mse + ssim + 0.7 * gme;
        if (out_size > 0) out[0] = (float)total;
        if (out_size > 1) out[1] = (float)mse;
        if (out_size > 2) out[2] = (float)ssim;
        if (out_size > 3) out[3] = (float)gme;
    }
}

// ---------------- launch ----------------
// Two independent branches run concurrently via graph-capturable stream fork.
// Branch A (critical path) is enqueued FIRST so its blocks lead dispatch:
//   branch A (stream 0):  fused_wh -> pass_d_ssim     (SSIM + MSE)
//   branch B (stream s2): sobel    -> gme             (edge loss)
extern "C" void kernel_launch(void* const* d_in, const int* in_sizes, int n_in,
                              void* d_out, int out_size) {
    const float* pred = (const float*)d_in[0];
    const float* targ = (const float*)d_in[1];
    float* out = (float*)d_out;

    static cudaStream_t s2 = 0;
    static cudaEvent_t evFork = 0, evJoin = 0;
    if (s2 == 0) {
        cudaStreamCreateWithFlags(&s2, cudaStreamNonBlocking);
        cudaEventCreateWithFlags(&evFork, cudaEventDisableTiming);
        cudaEventCreateWithFlags(&evJoin, cudaEventDisableTiming);
    }

    init_kernel<<<1, 64>>>();
    cudaEventRecord(evFork, 0);
    cudaStreamWaitEvent(s2, evFork, 0);

    // branch A on stream 0 (critical path — enqueued first)
    fused_wh<<<dim3(BB*DD, HCH), dim3(128, 2)>>>(pred, targ);
    pass_d_ssim<<<dim3(HH, BB, DCH), WW>>>();

    // branch B on s2
    sobel_kernel<<<dim3(WW/32, HH/8, BB*16), dim3(32, 8), 0, s2>>>(pred, targ);
    gme_kernel<<<1024, 256, 0, s2>>>();

    // join
    cudaEventRecord(evJoin, s2);
    cudaStreamWaitEvent(0, evJoin, 0);
    finalize_kernel<<<1, 32>>>(out, out_size);
}

// round 17
// speedup vs baseline: 1.5710x; 1.5710x over previous
#include <cuda_runtime.h>
#include <cuda_fp16.h>
#include <math.h>

// Problem constants
#define BB 2
#define DD 128
#define HH 128
#define WW 128
#define NVOX (BB*DD*HH*WW)          // 4194304
#define PLANE (HH*WW)               // 16384

// ---------------- static device scratch (no runtime allocation) ----------------
// interleaved per voxel: {gauss_wh(s), gauss_wh(s^2), gauss_wh(d), gauss_wh(d^2)}
__device__ __align__(16) float4 g_buf4[NVOX];
__device__ __align__(16) __half g_gm[2u*NVOX];  // gradient magnitude (fp16): pred, target
__device__ double g_part[3][64];    // partial sums: mse, ssim, gme
__device__ unsigned g_mm[4];        // minp, maxp, mint, maxt (float bits, all >0)

// ---------------- helpers ----------------
__device__ __forceinline__ int refl(int x) {      // jnp 'reflect' (no edge repeat)
    return x < 0 ? -x : (x > 127 ? 254 - x : x);
}

__device__ __forceinline__ void load_gauss(float* G) {
    if (threadIdx.x == 0 && threadIdx.y == 0) {
        float tmp[11]; float s = 0.f;
        #pragma unroll
        for (int i = 0; i < 11; i++) {
            float o = (float)(i - 5);
            tmp[i] = expf(-(o*o) / 4.5f);   // 2*1.5^2 = 4.5
            s += tmp[i];
        }
        #pragma unroll
        for (int i = 0; i < 11; i++) G[i] = tmp[i] / s;
    }
}

// Block-wide sum -> double partial slot (1D blocks, size multiple of 32, <=1024)
__device__ __forceinline__ void block_add(float v, int slot) {
    #pragma unroll
    for (int o = 16; o > 0; o >>= 1) v += __shfl_down_sync(0xffffffffu, v, o);
    __shared__ float red[32];
    int lane = threadIdx.x & 31, wid = threadIdx.x >> 5;
    if (lane == 0) red[wid] = v;
    __syncthreads();
    int nw = (blockDim.x + 31) >> 5;
    if (wid == 0) {
        float x = (lane < nw) ? red[lane] : 0.f;
        #pragma unroll
        for (int o = 16; o > 0; o >>= 1) x += __shfl_down_sync(0xffffffffu, x, o);
        if (lane == 0) atomicAdd(&g_part[slot][blockIdx.x & 63], (double)x);
    }
}

// ---------------- kernels ----------------
__global__ void init_kernel() {
    int t = threadIdx.x;
    if (t < 64) { g_part[0][t] = 0.0; g_part[1][t] = 0.0; g_part[2][t] = 0.0; }
    if (t == 0) {
        g_mm[0] = 0x7F800000u; g_mm[1] = 0u;
        g_mm[2] = 0x7F800000u; g_mm[3] = 0u;
    }
}

// Fused W+H Gaussian, ONE channel pair per block (z=0: s={p+t}, z=1: d={p-t}).
// TWO rows per step: pair staged into q[bp],q[bp+1] (4 row buffers, bp flips
// 0<->2), ONE barrier per pair, two outputs per window from win[12] (shift by
// 2). Only the scalar u staged (u^2 squares at read time). Global loads
// prefetched one pair ahead. MSE accumulated by d-pair blocks.
#define HCH 4
#define HROWS (HH/HCH)   // 32
__global__ __launch_bounds__(128) void fused_wh(const float* __restrict__ p,
                                                const float* __restrict__ t) {
    __shared__ float G[11];
    __shared__ float q[4][WW+10];   // [buf][5 zero | WW data | 5 zero]
    load_gauss(G);
    int bd = blockIdx.x;
    int h0 = blockIdx.y * HROWS;
    int cp = blockIdx.z;             // 0 -> s-pair, 1 -> d-pair
    int w  = threadIdx.x;
    size_t sbase = (size_t)bd * PLANE;
    float2* __restrict__ dst = reinterpret_cast<float2*>(g_buf4) + cp;

    // zero the padding once (never overwritten afterwards)
    if (w < 5) {
        #pragma unroll
        for (int bq = 0; bq < 4; bq++) {
            q[bq][w]      = 0.f;
            q[bq][WW+5+w] = 0.f;
        }
    }

    float2 win[12];
    float msea = 0.f;

    // pending pair registers (prefetched)
    int r0 = h0 - 5;
    float pv0=0.f, tv0=0.f, pv1=0.f, tv1=0.f;
    if (r0 >= 0)   { pv0 = p[sbase + (size_t)r0*WW + w];     tv0 = t[sbase + (size_t)r0*WW + w]; }
    { int r1 = r0 + 1; if (r1 >= 0 && r1 < HH) { pv1 = p[sbase + (size_t)r1*WW + w]; tv1 = t[sbase + (size_t)r1*WW + w]; } }
    int bp = 0;

    // STEP2: stage pending pair -> q[bp],q[bp+1], prefetch next pair, barrier,
    // W-conv both rows -> DA,DB. Race-free: buffer bp is rewritten 2 barriers
    // after its conv-read.
    #define STEP2(DA, DB)                                                               \
    {                                                                                   \
        int ra = r0, rb = r0 + 1;                                                       \
        bool oka = (ra >= 0 && ra < HH), okb = (rb >= 0 && rb < HH);                    \
        if (oka) {                                                                      \
            float u = cp ? (pv0 - tv0) : (pv0 + tv0);                                   \
            q[bp][w+5] = u;                                                             \
            if (cp && ra >= h0 && ra < h0 + HROWS) msea += u*u;                         \
        }                                                                               \
        if (okb) {                                                                      \
            float u = cp ? (pv1 - tv1) : (pv1 + tv1);                                   \
            q[bp+1][w+5] = u;                                                           \
            if (cp && rb >= h0 && rb < h0 + HROWS) msea += u*u;                         \
        }                                                                               \
        int rn0 = r0 + 2, rn1 = r0 + 3;                                                 \
        float pn0=0.f, tn0=0.f, pn1=0.f, tn1=0.f;                                       \
        if (rn0 >= 0 && rn0 < HH) { pn0 = p[sbase + (size_t)rn0*WW + w]; tn0 = t[sbase + (size_t)rn0*WW + w]; } \
        if (rn1 >= 0 && rn1 < HH) { pn1 = p[sbase + (size_t)rn1*WW + w]; tn1 = t[sbase + (size_t)rn1*WW + w]; } \
        __syncthreads();                                                                \
        float a0=0.f, a1=0.f, b0=0.f, b1=0.f;                                           \
        if (oka) {                                                                      \
            _Pragma("unroll")                                                           \
            for (int k = 0; k < 11; k++) {                                              \
                float v = q[bp][w+k]; float gv = G[k] * v;                              \
                a0 += gv; a1 += gv * v;                                                 \
            }                                                                           \
        }                                                                               \
        if (okb) {                                                                      \
            _Pragma("unroll")                                                           \
            for (int k = 0; k < 11; k++) {                                              \
                float v = q[bp+1][w+k]; float gv = G[k] * v;                            \
                b0 += gv; b1 += gv * v;                                                 \
            }                                                                           \
        }                                                                               \
        DA = make_float2(a0, a1); DB = make_float2(b0, b1);                             \
        pv0=pn0; tv0=tn0; pv1=pn1; tv1=tn1; r0 = rn0; bp ^= 2;                          \
    }

    // preload win[0..11] = rows h0-5 .. h0+6 (6 pairs)
    #pragma unroll
    for (int k = 0; k < 6; k++) {
        STEP2(win[2*k], win[2*k+1]);
    }

    // main loop: 2 output rows per iteration
    for (int h = h0; h < h0 + HROWS; h += 2) {
        float a0=0.f, a1=0.f, b0=0.f, b1=0.f;
        #pragma unroll
        for (int j = 0; j < 11; j++) {
            float g = G[j];
            a0 += g * win[j].x;   a1 += g * win[j].y;
            b0 += g * win[j+1].x; b1 += g * win[j+1].y;
        }
        dst[2u*(sbase + (size_t)h*WW + w)]     = make_float2(a0, a1);
        dst[2u*(sbase + (size_t)(h+1)*WW + w)] = make_float2(b0, b1);
        #pragma unroll
        for (int j = 0; j < 10; j++) win[j] = win[j+2];
        STEP2(win[10], win[11]);
    }
    #undef STEP2

    block_add(msea, 0);   // s-pair blocks contribute 0
}

// Gaussian along D of the float4 channels + fused SSIM map + reduction.
// SSIM from {gs, gs2, gd, gd2}:
//   mu_p^2+mu_t^2 = (gs^2+gd^2)/2,  2*mu_pt = (gs^2-gd^2)/2
//   2*sig_pt = ((gs2-gd2)-(gs^2-gd^2))/2,  sig_p+sig_t = ((gs2+gd2)-(gs^2+gd^2))/2
// grid: (HH, BB, DCH d-chunks), block: WW. One LDG.128 per ring step.
#define DCH 8
#define DROWS (DD/DCH)  // 16
__global__ __launch_bounds__(WW) void pass_d_ssim() {
    __shared__ float G[11];
    load_gauss(G); __syncthreads();
    int h = blockIdx.x, b = blockIdx.y, cz = blockIdx.z;
    int w = threadIdx.x;
    int d0 = cz * DROWS;
    size_t base0 = ((size_t)b*DD*HH + (size_t)h)*WW + w;
    const float4* __restrict__ src = g_buf4;

    float4 win[11];
    #pragma unroll
    for (int j = 0; j < 11; j++) {
        int d = d0 + j - 5;
        win[j] = (d >= 0 && d < DD)
            ? src[base0 + (size_t)d*PLANE] : make_float4(0.f,0.f,0.f,0.f);
    }

    float ssum = 0.f;
    for (int d = d0; d < d0 + DROWS; d++) {
        float gs=0.f, gs2=0.f, gd=0.f, gd2=0.f;
        #pragma unroll
        for (int j = 0; j < 11; j++) {
            float g = G[j];
            gs  += g * win[j].x; gs2 += g * win[j].y;
            gd  += g * win[j].z; gd2 += g * win[j].w;
        }
        float Av = gs*gs, Bv = gd*gd;
        float sumAB = Av + Bv, difAB = Av - Bv;
        float num = (0.5f*difAB + 1e-4f) * (0.5f*((gs2 - gd2) - difAB) + 9e-4f);
        float den = (0.5f*sumAB + 1e-4f) * (0.5f*((gs2 + gd2) - sumAB) + 9e-4f);
        ssum += num / den;

        int nd = d + 6;
        #pragma unroll
        for (int j = 0; j < 10; j++) win[j] = win[j+1];
        win[10] = (nd < DD)
            ? src[base0 + (size_t)nd*PLANE] : make_float4(0.f,0.f,0.f,0.f);
    }
    block_add(ssum, 1);
}

// Sobel gradient magnitude. ALL 10 d-planes preloaded with VECTORIZED loads
// (one LDG.128 per thread per plane + 20 halo scalars per volume) and a single
// barrier, then barrier-free compute with strength-reduced separable algebra.
// gm stored as fp16 (min/max computed on the ROUNDED value for consistency).
// grid: (WW/32, HH/8, BB*16), block: (32,8). Each block: 8 output planes.
__global__ __launch_bounds__(256) void sobel_kernel(const float* __restrict__ pred,
                                                    const float* __restrict__ targ) {
    // interior cols 4..35 (16B aligned), left halo col 3, right halo col 36
    __shared__ __align__(16) float tile[10][2][10][40];   // [plane][vol][row][col]
    int tx = threadIdx.x, ty = threadIdx.y;
    int tid = ty * 32 + tx;
    int w0 = blockIdx.x * 32, h0 = blockIdx.y * 8;
    int z = blockIdx.z;
    int b = z >> 4, d0 = (z & 15) * 8;

    // ---- load all 10 planes, one barrier ----
    {
        int v = tid >> 7;                 // volume handled by this half-block
        int u = tid & 127;
        const float* __restrict__ src = v ? targ : pred;
        bool isVec  = (u < 80);
        int rv = u >> 3, c4 = u & 7;      // vector role: row rv, 4-col group c4
        bool isHalo = (u >= 80 && u < 100);
        int e = u - 80;
        int rh = e >> 1, side = e & 1;    // halo role: row rh, side L/R
        int ghv = isVec  ? refl(h0 + rv - 1) : 0;
        int ghh = isHalo ? refl(h0 + rh - 1) : 0;
        int gwh = side ? refl(w0 + 32) : refl(w0 - 1);
        int colh = side ? 36 : 3;
        #pragma unroll
        for (int i = 0; i < 10; i++) {
            int gd = refl(d0 - 1 + i);
            size_t pb = ((size_t)b*DD + gd)*PLANE;
            if (isVec) {
                float4 val = *reinterpret_cast<const float4*>(src + pb + (size_t)ghv*WW + w0 + c4*4);
                *reinterpret_cast<float4*>(&tile[i][v][rv][4 + c4*4]) = val;
            } else if (isHalo) {
                tile[i][v][rh][colh] = src[pb + (size_t)ghh*WW + gwh];
            }
        }
    }
    __syncthreads();

    // ---- compute: 2 sequential volume passes, no barriers ----
    float mnv[2], mxv[2];
    #pragma unroll
    for (int v = 0; v < 2; v++) {
        float P[3][7];
        float mn = 3.4e38f, mx = 0.f;
        #pragma unroll
        for (int i = 0; i < 10; i++) {
            const int ri = i % 3;
            {
                float ws[3], wc[3], wo[3];
                #pragma unroll
                for (int j = 0; j < 3; j++) {
                    float x0 = tile[i][v][ty+j][tx+3];
                    float x1 = tile[i][v][ty+j][tx+4];
                    float x2 = tile[i][v][ty+j][tx+5];
                    wo[j] = x0 + x1 + x2;
                    wc[j] = x2 - x0;
                    ws[j] = wo[j] + x1;
                }
                P[ri][3] = wc[0] + wc[1] + wc[2];        // P4 = o(wc)
                P[ri][0] = P[ri][3] + wc[1];             // P1 = s(wc)
                P[ri][1] = ws[2] - ws[0];                // P2 = c(ws)
                P[ri][5] = ws[0] + ws[1] + ws[2];        // P6 = o(ws)
                P[ri][2] = P[ri][5] + ws[1];             // P3 = s(ws)
                P[ri][4] = wo[2] - wo[0];                // P5 = c(wo)
                P[ri][6] = wo[0] + 2.f*wo[1] + wo[2];    // P7 = s(wo)
            }
            if (i >= 2) {
                const int dm = (i - 2) % 3, dc = (i - 1) % 3, dp = ri;
                int d = d0 + i - 2;
                float B5 = P[dm][0] + P[dc][0] + P[dp][0];
                float gx = B5 + P[dc][0];                        // Sx
                float B4 = P[dm][1] + P[dc][1] + P[dp][1];
                float gy = B4 + P[dc][1];                        // Sy
                float gz = P[dp][2] - P[dm][2];                  // Sz
                float B1 = P[dm][3] + 2.f*P[dc][3] + P[dp][3];
                float B2 = P[dm][4] + 2.f*P[dc][4] + P[dp][4];
                float B3 = P[dp][5] - P[dm][5];
                float B6 = P[dp][6] - P[dm][6];

                float sB = B1*B1 + B2*B2 + B3*B3 + B4*B4 + B5*B5 + B6*B6;
                float acc = gx*gx + gy*gy + gz*gz + 2.f*sB + 9e-6f;
                float gm = sqrtf(acc);

                __half hv = __float2half_rn(gm);
                float gmr = __half2float(hv);    // rounded value (what gme will see)

                size_t vox = (((size_t)b*DD + d)*HH + (h0 + ty))*WW + (w0 + tx);
                g_gm[(size_t)v*NVOX + vox] = hv;
                mn = fminf(mn, gmr); mx = fmaxf(mx, gmr);
            }
        }
        mnv[v] = mn; mxv[v] = mx;
    }

    // block min/max reduction (positive floats -> uint ordering)
    float mn0 = mnv[0], mx0 = mxv[0], mn1 = mnv[1], mx1 = mxv[1];
    #pragma unroll
    for (int o = 16; o > 0; o >>= 1) {
        mn0 = fminf(mn0, __shfl_down_sync(0xffffffffu, mn0, o));
        mx0 = fmaxf(mx0, __shfl_down_sync(0xffffffffu, mx0, o));
        mn1 = fminf(mn1, __shfl_down_sync(0xffffffffu, mn1, o));
        mx1 = fmaxf(mx1, __shfl_down_sync(0xffffffffu, mx1, o));
    }
    __shared__ float s4[4][8];
    int lane = tid & 31, wid = tid >> 5;
    if (lane == 0) { s4[0][wid]=mn0; s4[1][wid]=mx0; s4[2][wid]=mn1; s4[3][wid]=mx1; }
    __syncthreads();
    if (tid == 0) {
        float a = s4[0][0], bx = s4[1][0], cmin = s4[2][0], dmax = s4[3][0];
        #pragma unroll
        for (int i = 1; i < 8; i++) {
            a = fminf(a, s4[0][i]); bx = fmaxf(bx, s4[1][i]);
            cmin = fminf(cmin, s4[2][i]); dmax = fmaxf(dmax, s4[3][i]);
        }
        atomicMin(&g_mm[0], __float_as_uint(a));
        atomicMax(&g_mm[1], __float_as_uint(bx));
        atomicMin(&g_mm[2], __float_as_uint(cmin));
        atomicMax(&g_mm[3], __float_as_uint(dmax));
    }
}

// GME: mean |norm(gm_p) - norm(gm_t)|. fp16 source read as float4 = 8 halves.
__global__ __launch_bounds__(256) void gme_kernel() {
    const float4* __restrict__ gm = reinterpret_cast<const float4*>(g_gm);
    float minp = __uint_as_float(g_mm[0]), maxp = __uint_as_float(g_mm[1]);
    float mint = __uint_as_float(g_mm[2]), maxt = __uint_as_float(g_mm[3]);
    float ip = 1.f / (maxp - minp + 1e-6f);
    float it = 1.f / (maxt - mint + 1e-6f);
    const int NV8 = NVOX / 8;   // float4 records of 8 halves, per volume
    float acc = 0.f;
    for (int i = blockIdx.x*blockDim.x + threadIdx.x; i < NV8;
         i += gridDim.x*blockDim.x) {
        float4 araw = gm[i];
        float4 braw = gm[NV8 + i];
        const __half2* ah = reinterpret_cast<const __half2*>(&araw);
        const __half2* bh = reinterpret_cast<const __half2*>(&braw);
        #pragma unroll
        for (int k = 0; k < 4; k++) {
            float2 a2 = __half22float2(ah[k]);
            float2 b2 = __half22float2(bh[k]);
            acc += fabsf((a2.x - minp)*ip - (b2.x - mint)*it);
            acc += fabsf((a2.y - minp)*ip - (b2.y - mint)*it);
        }
    }
    block_add(acc, 2);
}

__global__ void finalize_kernel(float* out, int out_size) {
    if (threadIdx.x == 0) {
        double s0 = 0.0, s1 = 0.0, s2 = 0.0;
        for (int i = 0; i < 64; i++) { s0 += g_part[0][i]; s1 += g_part[1][i]; s2 += g_part[2][i]; }
        const double inv = 1.0 / (double)NVOX;
        double mse  = s0 * inv;
        double ssim = 1.0 - s1 * inv;
        double gme  = 1e-6 + s2 * inv;
        double total = mse + ssim + 0.7 * gme;
        if (out_size > 0) out[0] = (float)total;
        if (out_size > 1) out[1] = (float)mse;
        if (out_size > 2) out[2] = (float)ssim;
        if (out_size > 3) out[3] = (float)gme;
    }
}

// ---------------- launch ----------------
// Two independent branches run concurrently via graph-capturable stream fork.
// Branch A (critical path) is enqueued FIRST so its blocks lead dispatch:
//   branch A (stream 0):  fused_wh -> pass_d_ssim     (SSIM + MSE)
//   branch B (stream s2): sobel    -> gme             (edge loss)
extern "C" void kernel_launch(void* const* d_in, const int* in_sizes, int n_in,
                              void* d_out, int out_size) {
    const float* pred = (const float*)d_in[0];
    const float* targ = (const float*)d_in[1];
    float* out = (float*)d_out;

    static cudaStream_t s2 = 0;
    static cudaEvent_t evFork = 0, evJoin = 0;
    if (s2 == 0) {
        cudaStreamCreateWithFlags(&s2, cudaStreamNonBlocking);
        cudaEventCreateWithFlags(&evFork, cudaEventDisableTiming);
        cudaEventCreateWithFlags(&evJoin, cudaEventDisableTiming);
    }

    init_kernel<<<1, 64>>>();
    cudaEventRecord(evFork, 0);
    cudaStreamWaitEvent(s2, evFork, 0);

    // branch A on stream 0 (critical path — enqueued first)
    fused_wh<<<dim3(BB*DD, HCH, 2), 128>>>(pred, targ);
    pass_d_ssim<<<dim3(HH, BB, DCH), WW>>>();

    // branch B on s2
    sobel_kernel<<<dim3(WW/32, HH/8, BB*16), dim3(32, 8), 0, s2>>>(pred, targ);
    gme_kernel<<<1024, 256, 0, s2>>>();

    // join
    cudaEventRecord(evJoin, s2);
    cudaStreamWaitEvent(0, evJoin, 0);
    finalize_kernel<<<1, 32>>>(out, out_size);
}